// round 10
// baseline (speedup 1.0000x reference)
#include <cuda_runtime.h>
#include <cuda_bf16.h>
#include <cstdint>

// Problem constants
#define LSEQ 128
#define BATCH 64
#define EMB 512
#define HID 512          // per direction
#define G4 2048          // 4*HID
#define MROWS 8192       // LSEQ*BATCH
#define NCOLS 4096       // 2 directions * 4H
#define NBLK_REC 128     // recurrence CTAs (2 dirs * 64)

// Packed fp32x2 helpers (sm_103a FFMA2 — only reachable via PTX)
__device__ __forceinline__ unsigned long long f32x2_pack_dup(float a) {
    unsigned long long p;
    asm("mov.b64 %0, {%1, %1};" : "=l"(p) : "r"(__float_as_uint(a)));
    return p;
}
__device__ __forceinline__ void f32x2_fma(unsigned long long& d,
                                          unsigned long long a,
                                          unsigned long long b) {
    asm("fma.rn.f32x2 %0, %1, %2, %3;" : "=l"(d) : "l"(a), "l"(b), "l"(d));
}
__device__ __forceinline__ void f32x2_unpack(unsigned long long p,
                                             float& lo, float& hi) {
    unsigned int l, h;
    asm("mov.b64 {%0, %1}, %2;" : "=r"(l), "=r"(h) : "l"(p));
    lo = __uint_as_float(l); hi = __uint_as_float(h);
}
union F4U2 { float4 f; unsigned long long u[2]; };

// ---------------------------------------------------------------------------
// Scratch (device globals; no allocations allowed)
// ---------------------------------------------------------------------------
__device__ float d_emb[(size_t)MROWS * EMB];          // 16 MB
__device__ float d_Xf [(size_t)MROWS * G4];           // 64 MB  (x@Wih_f^T + bias_f)
__device__ float d_Xb [(size_t)MROWS * G4];           // 64 MB
__device__ float d_h  [2 * 2 * BATCH * HID];          // [buf][dir][b][k]
__device__ volatile unsigned int d_bar_count;
__device__ volatile unsigned int d_bar_gen;

// ---------------------------------------------------------------------------
// 1) Embedding gather
// ---------------------------------------------------------------------------
__global__ void k_embed(const int* __restrict__ data,
                        const float* __restrict__ table) {
    int i = blockIdx.x * blockDim.x + threadIdx.x;      // float4 index
    if (i >= MROWS * (EMB / 4)) return;
    int m  = i >> 7;            // EMB/4 = 128 float4 per row
    int e4 = i & 127;
    int w  = data[m];
    float4 v = make_float4(0.f, 0.f, 0.f, 0.f);
    if (w >= 0) v = *(const float4*)(table + (size_t)w * EMB + e4 * 4);
    *(float4*)(d_emb + (size_t)m * EMB + e4 * 4) = v;
}

// ---------------------------------------------------------------------------
// 2) Input projection GEMM with packed f32x2 FMA.
//    BM=128, BN=128, BK=8, 256 threads, micro-tile 4m x 16n (8 n-pairs).
// ---------------------------------------------------------------------------
__global__ void __launch_bounds__(256, 2)
k_gemm(const float* __restrict__ Wf, const float* __restrict__ Wb,
       const float* __restrict__ bihf, const float* __restrict__ bhhf,
       const float* __restrict__ bihb, const float* __restrict__ bhhb) {
    __shared__ float As[8][132];
    __shared__ float Bs[8][132];

    const int tid = threadIdx.x;
    const int n0 = blockIdx.x * 128;
    const int m0 = blockIdx.y * 128;
    const int tx = tid & 7,  ty = tid >> 3;     // 8 x 32 threads
    const int lm = tid >> 1;                    // 0..127 : tile row for loads
    const int lk = (tid & 1) * 4;               // 0 or 4 : k offset for loads

    const int gn = n0 + lm;
    const float* wrow = (gn < G4) ? (Wf + (size_t)gn * EMB)
                                  : (Wb + (size_t)(gn - G4) * EMB);
    const float* arow = d_emb + (size_t)(m0 + lm) * EMB;

    unsigned long long acc2[4][8];
#pragma unroll
    for (int i = 0; i < 4; i++)
#pragma unroll
        for (int j = 0; j < 8; j++) acc2[i][j] = 0ull;

    for (int k0 = 0; k0 < EMB; k0 += 8) {
        float4 av = *(const float4*)(arow + k0 + lk);
        float4 bv = *(const float4*)(wrow + k0 + lk);
        __syncthreads();
        As[lk + 0][lm] = av.x; As[lk + 1][lm] = av.y;
        As[lk + 2][lm] = av.z; As[lk + 3][lm] = av.w;
        Bs[lk + 0][lm] = bv.x; Bs[lk + 1][lm] = bv.y;
        Bs[lk + 2][lm] = bv.z; Bs[lk + 3][lm] = bv.w;
        __syncthreads();
#pragma unroll
        for (int kk = 0; kk < 8; kk++) {
            float4 af = *(const float4*)&As[kk][ty * 4];
            F4U2 bq[4];
            bq[0].f = *(const float4*)&Bs[kk][tx * 16     ];
            bq[1].f = *(const float4*)&Bs[kk][tx * 16 + 4 ];
            bq[2].f = *(const float4*)&Bs[kk][tx * 16 + 8 ];
            bq[3].f = *(const float4*)&Bs[kk][tx * 16 + 12];
            float a[4] = {af.x, af.y, af.z, af.w};
#pragma unroll
            for (int i = 0; i < 4; i++) {
                unsigned long long pa = f32x2_pack_dup(a[i]);
#pragma unroll
                for (int j = 0; j < 8; j++)
                    f32x2_fma(acc2[i][j], pa, bq[j >> 1].u[j & 1]);
            }
        }
    }

    // Epilogue: unpack, add bias, write to Xf/Xb
    const bool fwd = (n0 < G4);
    const int nb = fwd ? n0 : (n0 - G4);
    const float* bi = fwd ? bihf : bihb;
    const float* bh = fwd ? bhhf : bhhb;
    float* dstbase = fwd ? d_Xf : d_Xb;
#pragma unroll
    for (int i = 0; i < 4; i++) {
        int m = m0 + ty * 4 + i;
        float* drow = dstbase + (size_t)m * G4 + nb + tx * 16;
#pragma unroll
        for (int j = 0; j < 8; j++) {
            int n = nb + tx * 16 + 2 * j;
            float lo, hi;
            f32x2_unpack(acc2[i][j], lo, hi);
            drow[2 * j    ] = lo + bi[n    ] + bh[n    ];
            drow[2 * j + 1] = hi + bi[n + 1] + bh[n + 1];
        }
    }
}

// ---------------------------------------------------------------------------
// 3) Init: zero h buffer 0 (both dirs), reset barrier.
// ---------------------------------------------------------------------------
__global__ void k_init() {
    int i = blockIdx.x * blockDim.x + threadIdx.x;
    if (i < 2 * BATCH * HID) d_h[i] = 0.f;
    if (i == 0) { d_bar_count = 0u; d_bar_gen = 0u; }
}

// ---------------------------------------------------------------------------
// 4) Persistent recurrence, packed f32x2 FMA.
//    128 CTAs, 128 threads; micro-tile 2b x 8n (4 n-pairs).
// ---------------------------------------------------------------------------
#define SM_WS   (512 * 32)          // Ws: [512][32]
#define SM_HS   (64 * 68)           // h chunk [b][k(64) pad 68]
#define SM_CS   (64 * 33)           // gate results [b][32 pad 33]
#define SM_CC   (64 * 8)            // cell state
#define SMEM_RECUR ((SM_WS + SM_HS + SM_CS + SM_CC) * 4)

__global__ void __launch_bounds__(128, 1)
k_recur(const float* __restrict__ Whf, const float* __restrict__ Whb,
        const float* __restrict__ mask, float* __restrict__ out) {
    extern __shared__ float sm[];
    float* Ws  = sm;                    // [512][32]
    float* h_s = Ws + SM_WS;            // [64][68]
    float* Cs  = h_s + SM_HS;           // [64][33]
    float* c_s = Cs + SM_CS;            // [64][8]

    const int tid = threadIdx.x;
    const int dir = blockIdx.x >> 6;
    const int u0  = (blockIdx.x & 63) * 8;
    const float* Wsrc = dir ? Whb : Whf;
    const float* X    = dir ? d_Xb : d_Xf;

    // One-time: load Whh slice transposed into Ws[k][j]
    {
        int j  = tid & 31;                              // gate*8 + unit
        int ks = (tid >> 5) * 128;                      // 4 k-slices of 128
        int grow = (j >> 3) * HID + u0 + (j & 7);       // Whh row
        const float* src = Wsrc + (size_t)grow * HID;
#pragma unroll 4
        for (int kk = 0; kk < 128; kk += 4) {
            float4 v = *(const float4*)(src + ks + kk);
            Ws[(ks + kk + 0) * 32 + j] = v.x;
            Ws[(ks + kk + 1) * 32 + j] = v.y;
            Ws[(ks + kk + 2) * 32 + j] = v.z;
            Ws[(ks + kk + 3) * 32 + j] = v.w;
        }
    }
    for (int i = tid; i < 64 * 8; i += 128) c_s[i] = 0.f;
    __syncthreads();

    const int tx = tid & 3,  ty = tid >> 2;    // 4 x 32 threads
    const int c0 = tx * 8,   b0 = ty * 2;      // 2b x 8n micro-tile
    const int lkq = tid & 15, lbr = tid >> 4;  // h-chunk load mapping

    for (int step = 0; step < LSEQ; step++) {
        const int tcur = dir ? (LSEQ - 1 - step) : step;
        const int cur = step & 1, nxt = cur ^ 1;
        const float* hsrc = d_h + (size_t)(cur * 2 + dir) * BATCH * HID;
        float*       hdst = d_h + (size_t)(nxt * 2 + dir) * BATCH * HID;

        unsigned long long acc2[2][4];
#pragma unroll
        for (int i = 0; i < 2; i++)
#pragma unroll
            for (int j = 0; j < 4; j++) acc2[i][j] = 0ull;

        for (int kb = 0; kb < HID; kb += 64) {
            __syncthreads();
            // stage h chunk [64 b][64 k] -> h_s (coalesced global)
#pragma unroll
            for (int p = 0; p < 8; p++) {
                int b = p * 8 + lbr;
                float4 v = *(const float4*)(hsrc + (size_t)b * HID + kb + lkq * 4);
                *(float4*)&h_s[b * 68 + lkq * 4] = v;
            }
            __syncthreads();
#pragma unroll
            for (int k4 = 0; k4 < 64; k4 += 4) {
                float4 av0 = *(const float4*)&h_s[(b0    ) * 68 + k4];
                float4 av1 = *(const float4*)&h_s[(b0 + 1) * 68 + k4];
                const float* a0 = (const float*)&av0;
                const float* a1 = (const float*)&av1;
#pragma unroll
                for (int kk = 0; kk < 4; kk++) {
                    F4U2 w0, w1;
                    w0.f = *(const float4*)&Ws[(kb + k4 + kk) * 32 + c0    ];
                    w1.f = *(const float4*)&Ws[(kb + k4 + kk) * 32 + c0 + 4];
                    unsigned long long pa0 = f32x2_pack_dup(a0[kk]);
                    unsigned long long pa1 = f32x2_pack_dup(a1[kk]);
                    f32x2_fma(acc2[0][0], pa0, w0.u[0]);
                    f32x2_fma(acc2[0][1], pa0, w0.u[1]);
                    f32x2_fma(acc2[0][2], pa0, w1.u[0]);
                    f32x2_fma(acc2[0][3], pa0, w1.u[1]);
                    f32x2_fma(acc2[1][0], pa1, w0.u[0]);
                    f32x2_fma(acc2[1][1], pa1, w0.u[1]);
                    f32x2_fma(acc2[1][2], pa1, w1.u[0]);
                    f32x2_fma(acc2[1][3], pa1, w1.u[1]);
                }
            }
        }

        // gate results -> Cs (pairs are adjacent cols)
#pragma unroll
        for (int i = 0; i < 2; i++)
#pragma unroll
            for (int j = 0; j < 4; j++) {
                float lo, hi;
                f32x2_unpack(acc2[i][j], lo, hi);
                Cs[(b0 + i) * 33 + c0 + 2 * j    ] = lo;
                Cs[(b0 + i) * 33 + c0 + 2 * j + 1] = hi;
            }
        __syncthreads();

        // epilogue: 512 (b, unit) items, 4 per thread
#pragma unroll
        for (int it = tid; it < 512; it += 128) {
            int b = it >> 3, uu = it & 7;
            size_t xbase = ((size_t)(tcur * BATCH + b)) * G4 + u0 + uu;
            float gi = Cs[b * 33 + uu]        + X[xbase];
            float gf = Cs[b * 33 + 8  + uu]   + X[xbase + 512];
            float gg = Cs[b * 33 + 16 + uu]   + X[xbase + 1024];
            float go = Cs[b * 33 + 24 + uu]   + X[xbase + 1536];
            float si = 1.f / (1.f + __expf(-gi));
            float sf = 1.f / (1.f + __expf(-gf));
            float so = 1.f / (1.f + __expf(-go));
            float c  = sf * c_s[b * 8 + uu] + si * tanhf(gg);
            float h  = so * tanhf(c);
            float m  = mask[tcur * BATCH + b];
            c *= m; h *= m;
            c_s[b * 8 + uu] = c;
            hdst[(size_t)b * HID + u0 + uu] = h;
            out[((size_t)(tcur * BATCH + b)) * 1024 + dir * HID + u0 + uu] = h;
        }

        // ---- grid barrier (release h writes, acquire for next step) ----
        __threadfence();
        __syncthreads();
        if (tid == 0) {
            const unsigned int target = (unsigned)(step + 1);
            unsigned int arrived =
                atomicAdd((unsigned int*)&d_bar_count, 1u) + 1u;
            if (arrived == (unsigned)NBLK_REC * target) {
                __threadfence();                 // order before release
                atomicAdd((unsigned int*)&d_bar_gen, 1u);
            } else {
                unsigned ns = 64;
                while (d_bar_gen < target) {     // volatile read
                    __nanosleep(ns);
                    if (ns < 1024) ns <<= 1;     // backoff, cap 1us
                }
            }
        }
        __syncthreads();
        __threadfence();
    }
}

// ---------------------------------------------------------------------------
// Launch
// ---------------------------------------------------------------------------
extern "C" void kernel_launch(void* const* d_in, const int* in_sizes, int n_in,
                              void* d_out, int out_size) {
    const int*   data  = (const int*)  d_in[0];
    const float* mask  = (const float*)d_in[1];
    const float* table = (const float*)d_in[2];
    const float* Wih_f = (const float*)d_in[3];
    const float* Whh_f = (const float*)d_in[4];
    const float* bih_f = (const float*)d_in[5];
    const float* bhh_f = (const float*)d_in[6];
    const float* Wih_b = (const float*)d_in[7];
    const float* Whh_b = (const float*)d_in[8];
    const float* bih_b = (const float*)d_in[9];
    const float* bhh_b = (const float*)d_in[10];
    float* out = (float*)d_out;

    (void)in_sizes; (void)n_in; (void)out_size;

    cudaFuncSetAttribute(k_recur, cudaFuncAttributeMaxDynamicSharedMemorySize,
                         SMEM_RECUR);

    k_embed<<<(MROWS * (EMB / 4) + 255) / 256, 256>>>(data, table);

    dim3 ggrid(NCOLS / 128, MROWS / 128);   // 32 x 64
    k_gemm<<<ggrid, 256>>>(Wih_f, Wih_b, bih_f, bhh_f, bih_b, bhh_b);

    k_init<<<256, 256>>>();

    k_recur<<<NBLK_REC, 128, SMEM_RECUR>>>(Whh_f, Whh_b, mask, out);
}

// round 12
// speedup vs baseline: 2.7337x; 2.7337x over previous
#include <cuda_runtime.h>
#include <cuda_bf16.h>
#include <cstdint>

// Problem constants
#define LSEQ 128
#define BATCH 64
#define EMB 512
#define HID 512          // per direction
#define G4 2048          // 4*HID
#define MROWS 8192       // LSEQ*BATCH
#define NCOLS 4096       // 2 directions * 4H
#define NBLK_REC 128     // recurrence CTAs (2 dirs * 64)

// ---------------------------------------------------------------------------
// Scratch (device globals; no allocations allowed)
// ---------------------------------------------------------------------------
__device__ __nv_bfloat16 d_Ahi[(size_t)MROWS * EMB];   // 8 MB emb hi
__device__ __nv_bfloat16 d_Alo[(size_t)MROWS * EMB];   // 8 MB emb lo
__device__ __nv_bfloat16 d_Whi[(size_t)NCOLS * EMB];   // 4 MB Wih (f|b) hi
__device__ __nv_bfloat16 d_Wlo[(size_t)NCOLS * EMB];   // 4 MB Wih (f|b) lo
__device__ float d_Xf [(size_t)MROWS * G4];            // 64 MB
__device__ float d_Xb [(size_t)MROWS * G4];            // 64 MB
__device__ float d_h  [2 * 2 * BATCH * HID];           // [buf][dir][b][k]
__device__ volatile unsigned int d_bar_count;
__device__ volatile unsigned int d_bar_gen;

// ---------------------------------------------------------------------------
// bf16 hi/lo split helper
// ---------------------------------------------------------------------------
__device__ __forceinline__ void split4(float4 v, uint2& hi, uint2& lo) {
    __nv_bfloat16 hx = __float2bfloat16_rn(v.x);
    __nv_bfloat16 hy = __float2bfloat16_rn(v.y);
    __nv_bfloat16 hz = __float2bfloat16_rn(v.z);
    __nv_bfloat16 hw = __float2bfloat16_rn(v.w);
    __nv_bfloat16 lx = __float2bfloat16_rn(v.x - __bfloat162float(hx));
    __nv_bfloat16 ly = __float2bfloat16_rn(v.y - __bfloat162float(hy));
    __nv_bfloat16 lz = __float2bfloat16_rn(v.z - __bfloat162float(hz));
    __nv_bfloat16 lw = __float2bfloat16_rn(v.w - __bfloat162float(hw));
    hi.x = (uint32_t)__bfloat16_as_ushort(hx) | ((uint32_t)__bfloat16_as_ushort(hy) << 16);
    hi.y = (uint32_t)__bfloat16_as_ushort(hz) | ((uint32_t)__bfloat16_as_ushort(hw) << 16);
    lo.x = (uint32_t)__bfloat16_as_ushort(lx) | ((uint32_t)__bfloat16_as_ushort(ly) << 16);
    lo.y = (uint32_t)__bfloat16_as_ushort(lz) | ((uint32_t)__bfloat16_as_ushort(lw) << 16);
}

// ---------------------------------------------------------------------------
// 1) Embedding gather fused with bf16 hi/lo split
// ---------------------------------------------------------------------------
__global__ void k_embed_cvt(const int* __restrict__ data,
                            const float* __restrict__ table) {
    int i = blockIdx.x * blockDim.x + threadIdx.x;      // float4 index
    if (i >= MROWS * (EMB / 4)) return;
    int m  = i >> 7;
    int e4 = i & 127;
    int w  = data[m];
    float4 v = make_float4(0.f, 0.f, 0.f, 0.f);
    if (w >= 0) v = *(const float4*)(table + (size_t)w * EMB + e4 * 4);
    uint2 hi, lo;
    split4(v, hi, lo);
    *(uint2*)(d_Ahi + (size_t)m * EMB + e4 * 4) = hi;
    *(uint2*)(d_Alo + (size_t)m * EMB + e4 * 4) = lo;
}

// ---------------------------------------------------------------------------
// 1b) Wih stack + split: rows [0,2048) = Wih_f, [2048,4096) = Wih_b
// ---------------------------------------------------------------------------
__global__ void k_wcvt(const float* __restrict__ Wf, const float* __restrict__ Wb) {
    int i = blockIdx.x * blockDim.x + threadIdx.x;      // float4 index
    if (i >= NCOLS * (EMB / 4)) return;
    int m  = i >> 7;
    int e4 = i & 127;
    const float* src = (m < G4) ? (Wf + (size_t)m * EMB)
                                : (Wb + (size_t)(m - G4) * EMB);
    float4 v = *(const float4*)(src + e4 * 4);
    uint2 hi, lo;
    split4(v, hi, lo);
    *(uint2*)(d_Whi + (size_t)m * EMB + e4 * 4) = hi;
    *(uint2*)(d_Wlo + (size_t)m * EMB + e4 * 4) = lo;
}

// ---------------------------------------------------------------------------
// 2) Split-bf16 mma.sync GEMM (HMMA path; no tcgen05 — ptxas targets sm_103).
//    X[m][n] = emb[m][:] . W[n][:] + bias[n]
//    CTA 128M x 128N, 8 warps (4x2), warp tile 32M x 64N.
//    3 accumulate passes: hi*hi + hi*lo + lo*hi into fp32 accumulators.
// ---------------------------------------------------------------------------
#define KC 32           // k-chunk (elements)
#define SASTR 40        // smem row stride in bf16 (80 B, conflict-free + 16B-aligned)

__device__ __forceinline__ void mma16816(float* d, const uint32_t* a,
                                         const uint32_t* b) {
    asm volatile(
        "mma.sync.aligned.m16n8k16.row.col.f32.bf16.bf16.f32 "
        "{%0,%1,%2,%3}, {%4,%5,%6,%7}, {%8,%9}, {%0,%1,%2,%3};"
        : "+f"(d[0]), "+f"(d[1]), "+f"(d[2]), "+f"(d[3])
        : "r"(a[0]), "r"(a[1]), "r"(a[2]), "r"(a[3]), "r"(b[0]), "r"(b[1]));
}

__global__ void __launch_bounds__(256, 1)
k_gemm_mma(const float* __restrict__ bihf, const float* __restrict__ bhhf,
           const float* __restrict__ bihb, const float* __restrict__ bhhb) {
    __shared__ __nv_bfloat16 sAh[128 * SASTR];
    __shared__ __nv_bfloat16 sAl[128 * SASTR];
    __shared__ __nv_bfloat16 sBh[128 * SASTR];
    __shared__ __nv_bfloat16 sBl[128 * SASTR];

    const int tid  = threadIdx.x;
    const int wid  = tid >> 5, lane = tid & 31;
    const int g    = lane >> 2, t4 = lane & 3;   // mma fragment coords
    const int wm   = wid & 3,  wn = wid >> 2;    // warp grid 4(M) x 2(N)
    const int n0   = blockIdx.x * 128;
    const int m0   = blockIdx.y * 128;

    const char* Ah = (const char*)(d_Ahi + (size_t)m0 * EMB);
    const char* Al = (const char*)(d_Alo + (size_t)m0 * EMB);
    const char* Bh = (const char*)(d_Whi + (size_t)n0 * EMB);
    const char* Bl = (const char*)(d_Wlo + (size_t)n0 * EMB);

    float acc[2][8][4];
#pragma unroll
    for (int mt = 0; mt < 2; mt++)
#pragma unroll
        for (int nt = 0; nt < 8; nt++)
#pragma unroll
            for (int r = 0; r < 4; r++) acc[mt][nt][r] = 0.f;

    for (int ch = 0; ch < EMB / KC; ch++) {
        const int kb = ch * KC * 2;              // byte offset within 1024B row
        __syncthreads();
        // stage 4 tiles of 128 rows x 32 bf16 (row = i>>2, quad = i&3)
#pragma unroll
        for (int i = tid; i < 512; i += 256) {
            int row = i >> 2, q = i & 3;
            size_t gsrc = (size_t)row * 1024 + kb + q * 16;
            int sdst = row * SASTR + q * 8;      // elements
            *(uint4*)&sAh[sdst] = *(const uint4*)(Ah + gsrc);
            *(uint4*)&sAl[sdst] = *(const uint4*)(Al + gsrc);
            *(uint4*)&sBh[sdst] = *(const uint4*)(Bh + gsrc);
            *(uint4*)&sBl[sdst] = *(const uint4*)(Bl + gsrc);
        }
        __syncthreads();

#pragma unroll
        for (int ks = 0; ks < KC / 16; ks++) {
            const int ko = ks * 16;
            // A fragments for 2 m-tiles (hi and lo)
            uint32_t ah[2][4], al[2][4];
#pragma unroll
            for (int mt = 0; mt < 2; mt++) {
                int r0 = (wm * 32 + mt * 16 + g) * SASTR + ko + 2 * t4;
                int r1 = (wm * 32 + mt * 16 + g + 8) * SASTR + ko + 2 * t4;
                ah[mt][0] = *(const uint32_t*)&sAh[r0];
                ah[mt][1] = *(const uint32_t*)&sAh[r1];
                ah[mt][2] = *(const uint32_t*)&sAh[r0 + 8];
                ah[mt][3] = *(const uint32_t*)&sAh[r1 + 8];
                al[mt][0] = *(const uint32_t*)&sAl[r0];
                al[mt][1] = *(const uint32_t*)&sAl[r1];
                al[mt][2] = *(const uint32_t*)&sAl[r0 + 8];
                al[mt][3] = *(const uint32_t*)&sAl[r1 + 8];
            }
#pragma unroll
            for (int nt = 0; nt < 8; nt++) {
                int rb = (wn * 64 + nt * 8 + g) * SASTR + ko + 2 * t4;
                uint32_t bh[2], bl[2];
                bh[0] = *(const uint32_t*)&sBh[rb];
                bh[1] = *(const uint32_t*)&sBh[rb + 8];
                bl[0] = *(const uint32_t*)&sBl[rb];
                bl[1] = *(const uint32_t*)&sBl[rb + 8];
                // hh, hl, lh — interleaved across m-tiles to space acc reuse
                mma16816(acc[0][nt], ah[0], bh);
                mma16816(acc[1][nt], ah[1], bh);
                mma16816(acc[0][nt], ah[0], bl);
                mma16816(acc[1][nt], ah[1], bl);
                mma16816(acc[0][nt], al[0], bh);
                mma16816(acc[1][nt], al[1], bh);
            }
        }
    }

    // Epilogue: add bias, store fp32
    const bool fwd = (n0 < G4);
    const int nb = fwd ? n0 : (n0 - G4);
    const float* bi = fwd ? bihf : bihb;
    const float* bh = fwd ? bhhf : bhhb;
    float* dstbase = fwd ? d_Xf : d_Xb;
#pragma unroll
    for (int nt = 0; nt < 8; nt++) {
        int n = nb + wn * 64 + nt * 8 + 2 * t4;
        float b0 = bi[n] + bh[n];
        float b1 = bi[n + 1] + bh[n + 1];
#pragma unroll
        for (int mt = 0; mt < 2; mt++) {
            int mr0 = m0 + wm * 32 + mt * 16 + g;
            float2 v0 = make_float2(acc[mt][nt][0] + b0, acc[mt][nt][1] + b1);
            float2 v1 = make_float2(acc[mt][nt][2] + b0, acc[mt][nt][3] + b1);
            *(float2*)(dstbase + (size_t)mr0 * G4 + n) = v0;
            *(float2*)(dstbase + (size_t)(mr0 + 8) * G4 + n) = v1;
        }
    }
}

// ---------------------------------------------------------------------------
// 3) Init: zero h buffer 0 (both dirs), reset barrier.
// ---------------------------------------------------------------------------
__global__ void k_init() {
    int i = blockIdx.x * blockDim.x + threadIdx.x;
    if (i < 2 * BATCH * HID) d_h[i] = 0.f;
    if (i == 0) { d_bar_count = 0u; d_bar_gen = 0u; }
}

// ---------------------------------------------------------------------------
// 4) Persistent recurrence (R5 scalar version — known good).
// ---------------------------------------------------------------------------
#define SM_WS   (512 * 32)          // Ws: [512][32]
#define SM_HS   (64 * 68)           // h chunk [b][k(64) pad 68]
#define SM_CS   (64 * 33)           // gate results [b][32 pad 33]
#define SM_CC   (64 * 8)            // cell state
#define SMEM_RECUR ((SM_WS + SM_HS + SM_CS + SM_CC) * 4)

__global__ void __launch_bounds__(128, 1)
k_recur(const float* __restrict__ Whf, const float* __restrict__ Whb,
        const float* __restrict__ mask, float* __restrict__ out) {
    extern __shared__ float smr[];
    float* Ws  = smr;                   // [512][32]
    float* h_s = Ws + SM_WS;            // [64][68]
    float* Cs  = h_s + SM_HS;           // [64][33]
    float* c_s = Cs + SM_CS;            // [64][8]

    const int tid = threadIdx.x;
    const int dir = blockIdx.x >> 6;
    const int u0  = (blockIdx.x & 63) * 8;
    const float* Wsrc = dir ? Whb : Whf;
    const float* X    = dir ? d_Xb : d_Xf;

    // One-time: load Whh slice transposed into Ws[k][j]
    {
        int j  = tid & 31;                              // gate*8 + unit
        int ks = (tid >> 5) * 128;                      // 4 k-slices of 128
        int grow = (j >> 3) * HID + u0 + (j & 7);       // Whh row
        const float* src = Wsrc + (size_t)grow * HID;
#pragma unroll 4
        for (int kk = 0; kk < 128; kk += 4) {
            float4 v = *(const float4*)(src + ks + kk);
            Ws[(ks + kk + 0) * 32 + j] = v.x;
            Ws[(ks + kk + 1) * 32 + j] = v.y;
            Ws[(ks + kk + 2) * 32 + j] = v.z;
            Ws[(ks + kk + 3) * 32 + j] = v.w;
        }
    }
    for (int i = tid; i < 64 * 8; i += 128) c_s[i] = 0.f;
    __syncthreads();

    const int tx = tid & 7, ty = tid >> 3;     // 8 x 16 threads
    const int b0 = ty * 4, c0 = tx * 4;        // 4x4 micro-tile
    const int lkq = tid & 15, lbr = tid >> 4;  // h-chunk load mapping

    for (int step = 0; step < LSEQ; step++) {
        const int tcur = dir ? (LSEQ - 1 - step) : step;
        const int cur = step & 1, nxt = cur ^ 1;
        const float* hsrc = d_h + (size_t)(cur * 2 + dir) * BATCH * HID;
        float*       hdst = d_h + (size_t)(nxt * 2 + dir) * BATCH * HID;

        float acc[4][4];
#pragma unroll
        for (int i = 0; i < 4; i++)
#pragma unroll
            for (int j = 0; j < 4; j++) acc[i][j] = 0.f;

        for (int kb = 0; kb < HID; kb += 64) {
            __syncthreads();
#pragma unroll
            for (int p = 0; p < 8; p++) {
                int b = p * 8 + lbr;
                float4 v = *(const float4*)(hsrc + (size_t)b * HID + kb + lkq * 4);
                *(float4*)&h_s[b * 68 + lkq * 4] = v;
            }
            __syncthreads();
#pragma unroll
            for (int k4 = 0; k4 < 64; k4 += 4) {
                float a[4][4], w[4][4];
#pragma unroll
                for (int i = 0; i < 4; i++)
                    *(float4*)a[i] = *(const float4*)&h_s[(b0 + i) * 68 + k4];
#pragma unroll
                for (int kk = 0; kk < 4; kk++)
                    *(float4*)w[kk] = *(const float4*)&Ws[(kb + k4 + kk) * 32 + c0];
#pragma unroll
                for (int i = 0; i < 4; i++)
#pragma unroll
                    for (int j = 0; j < 4; j++)
#pragma unroll
                        for (int kk = 0; kk < 4; kk++)
                            acc[i][j] += a[i][kk] * w[kk][j];
            }
        }

#pragma unroll
        for (int i = 0; i < 4; i++)
#pragma unroll
            for (int j = 0; j < 4; j++)
                Cs[(b0 + i) * 33 + (c0 + j)] = acc[i][j];
        __syncthreads();

#pragma unroll
        for (int it = tid; it < 512; it += 128) {
            int b = it >> 3, uu = it & 7;
            size_t xbase = ((size_t)(tcur * BATCH + b)) * G4 + u0 + uu;
            float gi = Cs[b * 33 + uu]        + X[xbase];
            float gf = Cs[b * 33 + 8  + uu]   + X[xbase + 512];
            float gg = Cs[b * 33 + 16 + uu]   + X[xbase + 1024];
            float go = Cs[b * 33 + 24 + uu]   + X[xbase + 1536];
            float si = 1.f / (1.f + __expf(-gi));
            float sf = 1.f / (1.f + __expf(-gf));
            float so = 1.f / (1.f + __expf(-go));
            float c  = sf * c_s[b * 8 + uu] + si * tanhf(gg);
            float h  = so * tanhf(c);
            float m  = mask[tcur * BATCH + b];
            c *= m; h *= m;
            c_s[b * 8 + uu] = c;
            hdst[(size_t)b * HID + u0 + uu] = h;
            out[((size_t)(tcur * BATCH + b)) * 1024 + dir * HID + u0 + uu] = h;
        }

        // ---- grid barrier ----
        __threadfence();
        __syncthreads();
        if (tid == 0) {
            const unsigned int target = (unsigned)(step + 1);
            unsigned int arrived =
                atomicAdd((unsigned int*)&d_bar_count, 1u) + 1u;
            if (arrived == (unsigned)NBLK_REC * target) {
                __threadfence();
                atomicAdd((unsigned int*)&d_bar_gen, 1u);
            } else {
                unsigned ns = 64;
                while (d_bar_gen < target) {
                    __nanosleep(ns);
                    if (ns < 1024) ns <<= 1;
                }
            }
        }
        __syncthreads();
        __threadfence();
    }
}

// ---------------------------------------------------------------------------
// Launch
// ---------------------------------------------------------------------------
extern "C" void kernel_launch(void* const* d_in, const int* in_sizes, int n_in,
                              void* d_out, int out_size) {
    const int*   data  = (const int*)  d_in[0];
    const float* mask  = (const float*)d_in[1];
    const float* table = (const float*)d_in[2];
    const float* Wih_f = (const float*)d_in[3];
    const float* Whh_f = (const float*)d_in[4];
    const float* bih_f = (const float*)d_in[5];
    const float* bhh_f = (const float*)d_in[6];
    const float* Wih_b = (const float*)d_in[7];
    const float* Whh_b = (const float*)d_in[8];
    const float* bih_b = (const float*)d_in[9];
    const float* bhh_b = (const float*)d_in[10];
    float* out = (float*)d_out;

    (void)in_sizes; (void)n_in; (void)out_size;

    cudaFuncSetAttribute(k_recur, cudaFuncAttributeMaxDynamicSharedMemorySize,
                         SMEM_RECUR);

    k_embed_cvt<<<(MROWS * (EMB / 4) + 255) / 256, 256>>>(data, table);
    k_wcvt<<<(NCOLS * (EMB / 4) + 255) / 256, 256>>>(Wih_f, Wih_b);

    dim3 ggrid(NCOLS / 128, MROWS / 128);   // 32 x 64
    k_gemm_mma<<<ggrid, 256>>>(bih_f, bhh_f, bih_b, bhh_b);

    k_init<<<256, 256>>>();

    k_recur<<<NBLK_REC, 128, SMEM_RECUR>>>(Whh_f, Whh_b, mask, out);
}

// round 13
// speedup vs baseline: 4.7120x; 1.7237x over previous
#include <cuda_runtime.h>
#include <cuda_bf16.h>
#include <cstdint>

// Problem constants
#define LSEQ 128
#define BATCH 64
#define EMB 512
#define HID 512          // per direction
#define G4 2048          // 4*HID
#define MROWS 8192       // LSEQ*BATCH
#define NCOLS 4096       // 2 directions * 4H
#define NBLK_REC 128     // recurrence CTAs

// ---------------------------------------------------------------------------
// Scratch (device globals; no allocations allowed)
// ---------------------------------------------------------------------------
__device__ __nv_bfloat16 d_Ahi[(size_t)MROWS * EMB];   // 8 MB emb hi
__device__ __nv_bfloat16 d_Alo[(size_t)MROWS * EMB];   // 8 MB emb lo
__device__ __nv_bfloat16 d_Whi[(size_t)NCOLS * EMB];   // 4 MB Wih (f|b) hi
__device__ __nv_bfloat16 d_Wlo[(size_t)NCOLS * EMB];   // 4 MB Wih (f|b) lo
__device__ float d_Xf [(size_t)MROWS * G4];            // 64 MB
__device__ float d_Xb [(size_t)MROWS * G4];            // 64 MB
__device__ __nv_bfloat16 d_hhi[2 * 2 * BATCH * HID];   // [buf][dir][b][k] hi
__device__ __nv_bfloat16 d_hlo[2 * 2 * BATCH * HID];   // [buf][dir][b][k] lo
__device__ volatile unsigned int d_bar_count;
__device__ volatile unsigned int d_bar_gen;

// ---------------------------------------------------------------------------
// bf16 hi/lo split helpers
// ---------------------------------------------------------------------------
__device__ __forceinline__ void split4(float4 v, uint2& hi, uint2& lo) {
    __nv_bfloat16 hx = __float2bfloat16_rn(v.x);
    __nv_bfloat16 hy = __float2bfloat16_rn(v.y);
    __nv_bfloat16 hz = __float2bfloat16_rn(v.z);
    __nv_bfloat16 hw = __float2bfloat16_rn(v.w);
    __nv_bfloat16 lx = __float2bfloat16_rn(v.x - __bfloat162float(hx));
    __nv_bfloat16 ly = __float2bfloat16_rn(v.y - __bfloat162float(hy));
    __nv_bfloat16 lz = __float2bfloat16_rn(v.z - __bfloat162float(hz));
    __nv_bfloat16 lw = __float2bfloat16_rn(v.w - __bfloat162float(hw));
    hi.x = (uint32_t)__bfloat16_as_ushort(hx) | ((uint32_t)__bfloat16_as_ushort(hy) << 16);
    hi.y = (uint32_t)__bfloat16_as_ushort(hz) | ((uint32_t)__bfloat16_as_ushort(hw) << 16);
    lo.x = (uint32_t)__bfloat16_as_ushort(lx) | ((uint32_t)__bfloat16_as_ushort(ly) << 16);
    lo.y = (uint32_t)__bfloat16_as_ushort(lz) | ((uint32_t)__bfloat16_as_ushort(lw) << 16);
}

// ---------------------------------------------------------------------------
// 1) Embedding gather fused with bf16 hi/lo split
// ---------------------------------------------------------------------------
__global__ void k_embed_cvt(const int* __restrict__ data,
                            const float* __restrict__ table) {
    int i = blockIdx.x * blockDim.x + threadIdx.x;
    if (i >= MROWS * (EMB / 4)) return;
    int m  = i >> 7;
    int e4 = i & 127;
    int w  = data[m];
    float4 v = make_float4(0.f, 0.f, 0.f, 0.f);
    if (w >= 0) v = *(const float4*)(table + (size_t)w * EMB + e4 * 4);
    uint2 hi, lo;
    split4(v, hi, lo);
    *(uint2*)(d_Ahi + (size_t)m * EMB + e4 * 4) = hi;
    *(uint2*)(d_Alo + (size_t)m * EMB + e4 * 4) = lo;
}

// ---------------------------------------------------------------------------
// 1b) Wih stack + split
// ---------------------------------------------------------------------------
__global__ void k_wcvt(const float* __restrict__ Wf, const float* __restrict__ Wb) {
    int i = blockIdx.x * blockDim.x + threadIdx.x;
    if (i >= NCOLS * (EMB / 4)) return;
    int m  = i >> 7;
    int e4 = i & 127;
    const float* src = (m < G4) ? (Wf + (size_t)m * EMB)
                                : (Wb + (size_t)(m - G4) * EMB);
    float4 v = *(const float4*)(src + e4 * 4);
    uint2 hi, lo;
    split4(v, hi, lo);
    *(uint2*)(d_Whi + (size_t)m * EMB + e4 * 4) = hi;
    *(uint2*)(d_Wlo + (size_t)m * EMB + e4 * 4) = lo;
}

// ---------------------------------------------------------------------------
// m16n8k16 bf16 mma
// ---------------------------------------------------------------------------
__device__ __forceinline__ void mma16816(float* d, const uint32_t* a,
                                         const uint32_t* b) {
    asm volatile(
        "mma.sync.aligned.m16n8k16.row.col.f32.bf16.bf16.f32 "
        "{%0,%1,%2,%3}, {%4,%5,%6,%7}, {%8,%9}, {%0,%1,%2,%3};"
        : "+f"(d[0]), "+f"(d[1]), "+f"(d[2]), "+f"(d[3])
        : "r"(a[0]), "r"(a[1]), "r"(a[2]), "r"(a[3]), "r"(b[0]), "r"(b[1]));
}

// ---------------------------------------------------------------------------
// 2) Split-bf16 mma.sync input GEMM (unchanged from R12)
// ---------------------------------------------------------------------------
#define KC 32
#define SASTR 40

__global__ void __launch_bounds__(256, 1)
k_gemm_mma(const float* __restrict__ bihf, const float* __restrict__ bhhf,
           const float* __restrict__ bihb, const float* __restrict__ bhhb) {
    __shared__ __nv_bfloat16 sAh[128 * SASTR];
    __shared__ __nv_bfloat16 sAl[128 * SASTR];
    __shared__ __nv_bfloat16 sBh[128 * SASTR];
    __shared__ __nv_bfloat16 sBl[128 * SASTR];

    const int tid  = threadIdx.x;
    const int wid  = tid >> 5, lane = tid & 31;
    const int g    = lane >> 2, t4 = lane & 3;
    const int wm   = wid & 3,  wn = wid >> 2;
    const int n0   = blockIdx.x * 128;
    const int m0   = blockIdx.y * 128;

    const char* Ah = (const char*)(d_Ahi + (size_t)m0 * EMB);
    const char* Al = (const char*)(d_Alo + (size_t)m0 * EMB);
    const char* Bh = (const char*)(d_Whi + (size_t)n0 * EMB);
    const char* Bl = (const char*)(d_Wlo + (size_t)n0 * EMB);

    float acc[2][8][4];
#pragma unroll
    for (int mt = 0; mt < 2; mt++)
#pragma unroll
        for (int nt = 0; nt < 8; nt++)
#pragma unroll
            for (int r = 0; r < 4; r++) acc[mt][nt][r] = 0.f;

    for (int ch = 0; ch < EMB / KC; ch++) {
        const int kb = ch * KC * 2;
        __syncthreads();
#pragma unroll
        for (int i = tid; i < 512; i += 256) {
            int row = i >> 2, q = i & 3;
            size_t gsrc = (size_t)row * 1024 + kb + q * 16;
            int sdst = row * SASTR + q * 8;
            *(uint4*)&sAh[sdst] = *(const uint4*)(Ah + gsrc);
            *(uint4*)&sAl[sdst] = *(const uint4*)(Al + gsrc);
            *(uint4*)&sBh[sdst] = *(const uint4*)(Bh + gsrc);
            *(uint4*)&sBl[sdst] = *(const uint4*)(Bl + gsrc);
        }
        __syncthreads();

#pragma unroll
        for (int ks = 0; ks < KC / 16; ks++) {
            const int ko = ks * 16;
            uint32_t ah[2][4], al[2][4];
#pragma unroll
            for (int mt = 0; mt < 2; mt++) {
                int r0 = (wm * 32 + mt * 16 + g) * SASTR + ko + 2 * t4;
                int r1 = (wm * 32 + mt * 16 + g + 8) * SASTR + ko + 2 * t4;
                ah[mt][0] = *(const uint32_t*)&sAh[r0];
                ah[mt][1] = *(const uint32_t*)&sAh[r1];
                ah[mt][2] = *(const uint32_t*)&sAh[r0 + 8];
                ah[mt][3] = *(const uint32_t*)&sAh[r1 + 8];
                al[mt][0] = *(const uint32_t*)&sAl[r0];
                al[mt][1] = *(const uint32_t*)&sAl[r1];
                al[mt][2] = *(const uint32_t*)&sAl[r0 + 8];
                al[mt][3] = *(const uint32_t*)&sAl[r1 + 8];
            }
#pragma unroll
            for (int nt = 0; nt < 8; nt++) {
                int rb = (wn * 64 + nt * 8 + g) * SASTR + ko + 2 * t4;
                uint32_t bh[2], bl[2];
                bh[0] = *(const uint32_t*)&sBh[rb];
                bh[1] = *(const uint32_t*)&sBh[rb + 8];
                bl[0] = *(const uint32_t*)&sBl[rb];
                bl[1] = *(const uint32_t*)&sBl[rb + 8];
                mma16816(acc[0][nt], ah[0], bh);
                mma16816(acc[1][nt], ah[1], bh);
                mma16816(acc[0][nt], ah[0], bl);
                mma16816(acc[1][nt], ah[1], bl);
                mma16816(acc[0][nt], al[0], bh);
                mma16816(acc[1][nt], al[1], bh);
            }
        }
    }

    const bool fwd = (n0 < G4);
    const int nb = fwd ? n0 : (n0 - G4);
    const float* bi = fwd ? bihf : bihb;
    const float* bh = fwd ? bhhf : bhhb;
    float* dstbase = fwd ? d_Xf : d_Xb;
#pragma unroll
    for (int nt = 0; nt < 8; nt++) {
        int n = nb + wn * 64 + nt * 8 + 2 * t4;
        float b0 = bi[n] + bh[n];
        float b1 = bi[n + 1] + bh[n + 1];
#pragma unroll
        for (int mt = 0; mt < 2; mt++) {
            int mr0 = m0 + wm * 32 + mt * 16 + g;
            float2 v0 = make_float2(acc[mt][nt][0] + b0, acc[mt][nt][1] + b1);
            float2 v1 = make_float2(acc[mt][nt][2] + b0, acc[mt][nt][3] + b1);
            *(float2*)(dstbase + (size_t)mr0 * G4 + n) = v0;
            *(float2*)(dstbase + (size_t)(mr0 + 8) * G4 + n) = v1;
        }
    }
}

// ---------------------------------------------------------------------------
// 3) Init: zero h split buffers, reset barrier. 512 x 256 threads.
// ---------------------------------------------------------------------------
__global__ void k_init() {
    int i = blockIdx.x * blockDim.x + threadIdx.x;
    if (i < 2 * 2 * BATCH * HID) {
        d_hhi[i] = __float2bfloat16(0.f);
        d_hlo[i] = __float2bfloat16(0.f);
    }
    if (i == 0) { d_bar_count = 0u; d_bar_gen = 0u; }
}

// ---------------------------------------------------------------------------
// 4) Persistent recurrence with split-bf16 mma.sync.
//    128 CTAs: dir(2) x batch-half(2) x unit-block(32, 16 units each).
//    CTA tile per step: 32 b x 64 gate-cols (4 gates x 16 units, gate-major).
//    256 threads = 8 warps (2m x 4n), warp tile 16b x 16n.
// ---------------------------------------------------------------------------
#define RSTR 520     // smem k-stride (bf16 elems); 1040 B rows, conflict-free

// smem layout (bytes):
//   sWh[64][520]  66560   sWl  66560   sHh[32][520] 33280  sHl 33280
//   Cs[32][68] f32 8704   c_s[32][16] f32 2048
#define RS_WH 0
#define RS_WL (RS_WH + 64 * RSTR)
#define RS_HH (RS_WL + 64 * RSTR)
#define RS_HL (RS_HH + 32 * RSTR)
#define RS_END (RS_HL + 32 * RSTR)              // bf16 elems
#define SMEM_RECUR (RS_END * 2 + (32 * 68 + 32 * 16) * 4)

__global__ void __launch_bounds__(256, 1)
k_recur_mma(const float* __restrict__ Whf, const float* __restrict__ Whb,
            const float* __restrict__ mask, float* __restrict__ out) {
    extern __shared__ __nv_bfloat16 smr[];
    __nv_bfloat16* sWh = smr + RS_WH;
    __nv_bfloat16* sWl = smr + RS_WL;
    __nv_bfloat16* sHh = smr + RS_HH;
    __nv_bfloat16* sHl = smr + RS_HL;
    float* Cs  = (float*)(smr + RS_END);        // [32][68]
    float* c_s = Cs + 32 * 68;                  // [32][16]

    const int tid  = threadIdx.x;
    const int wid  = tid >> 5, lane = tid & 31;
    const int g    = lane >> 2, t4 = lane & 3;
    const int wm   = wid & 1,  wn = wid >> 1;   // 2m x 4n warps
    const int dir  = blockIdx.x >> 6;
    const int q    = blockIdx.x & 63;
    const int b0g  = (q >> 5) * 32;             // batch-half base
    const int u0   = (q & 31) * 16;             // unit-block base
    const float* Wsrc = dir ? Whb : Whf;
    const float* X    = dir ? d_Xb : d_Xf;

    // One-time: load + split Whh slice. smem col n = gate*16 + uu.
    for (int it = 0; it < 32; it++) {
        int n    = it * 2 + (tid >> 7);
        int k4   = (tid & 127) * 4;
        int grow = (n >> 4) * HID + u0 + (n & 15);
        float4 v = *(const float4*)(Wsrc + (size_t)grow * HID + k4);
        uint2 hi, lo;
        split4(v, hi, lo);
        *(uint2*)&sWh[n * RSTR + k4] = hi;
        *(uint2*)&sWl[n * RSTR + k4] = lo;
    }
    for (int i = tid; i < 32 * 16; i += 256) c_s[i] = 0.f;
    __syncthreads();

    for (int step = 0; step < LSEQ; step++) {
        const int tcur = dir ? (LSEQ - 1 - step) : step;
        const int cur = step & 1, nxt = cur ^ 1;
        const __nv_bfloat16* hh = d_hhi + ((size_t)(cur * 2 + dir) * BATCH + b0g) * HID;
        const __nv_bfloat16* hl = d_hlo + ((size_t)(cur * 2 + dir) * BATCH + b0g) * HID;

        // stage h tile [32][512] hi+lo into smem
#pragma unroll
        for (int i = tid; i < 2048; i += 256) {
            int row = i >> 6, k8 = (i & 63) * 8;
            *(uint4*)&sHh[row * RSTR + k8] = *(const uint4*)(hh + (size_t)row * HID + k8);
            *(uint4*)&sHl[row * RSTR + k8] = *(const uint4*)(hl + (size_t)row * HID + k8);
        }
        __syncthreads();

        float acc[2][4];
#pragma unroll
        for (int nt = 0; nt < 2; nt++)
#pragma unroll
            for (int r = 0; r < 4; r++) acc[nt][r] = 0.f;

#pragma unroll 4
        for (int ks = 0; ks < 32; ks++) {
            const int ko = ks * 16;
            uint32_t ah[4], al[4];
            {
                int r0 = (wm * 16 + g) * RSTR + ko + 2 * t4;
                int r1 = r0 + 8 * RSTR;
                ah[0] = *(const uint32_t*)&sHh[r0];
                ah[1] = *(const uint32_t*)&sHh[r1];
                ah[2] = *(const uint32_t*)&sHh[r0 + 8];
                ah[3] = *(const uint32_t*)&sHh[r1 + 8];
                al[0] = *(const uint32_t*)&sHl[r0];
                al[1] = *(const uint32_t*)&sHl[r1];
                al[2] = *(const uint32_t*)&sHl[r0 + 8];
                al[3] = *(const uint32_t*)&sHl[r1 + 8];
            }
            uint32_t bh0[2], bl0[2], bh1[2], bl1[2];
            {
                int rb0 = (wn * 16 + g) * RSTR + ko + 2 * t4;
                int rb1 = rb0 + 8 * RSTR;
                bh0[0] = *(const uint32_t*)&sWh[rb0];
                bh0[1] = *(const uint32_t*)&sWh[rb0 + 8];
                bl0[0] = *(const uint32_t*)&sWl[rb0];
                bl0[1] = *(const uint32_t*)&sWl[rb0 + 8];
                bh1[0] = *(const uint32_t*)&sWh[rb1];
                bh1[1] = *(const uint32_t*)&sWh[rb1 + 8];
                bl1[0] = *(const uint32_t*)&sWl[rb1];
                bl1[1] = *(const uint32_t*)&sWl[rb1 + 8];
            }
            // two independent acc chains, interleaved
            mma16816(acc[0], ah, bh0);
            mma16816(acc[1], ah, bh1);
            mma16816(acc[0], ah, bl0);
            mma16816(acc[1], ah, bl1);
            mma16816(acc[0], al, bh0);
            mma16816(acc[1], al, bh1);
        }

        // acc -> Cs: rows wm*16+{g,g+8}, cols wn*16 + nt*8 + {2t4, 2t4+1}
#pragma unroll
        for (int nt = 0; nt < 2; nt++) {
            int col = wn * 16 + nt * 8 + 2 * t4;
            int r0 = (wm * 16 + g) * 68 + col;
            Cs[r0]      = acc[nt][0];
            Cs[r0 + 1]  = acc[nt][1];
            Cs[r0 + 8 * 68]     = acc[nt][2];
            Cs[r0 + 8 * 68 + 1] = acc[nt][3];
        }
        __syncthreads();

        // epilogue: 512 (b, uu) items, 2 per thread
#pragma unroll
        for (int it = tid; it < 512; it += 256) {
            int b = it >> 4, uu = it & 15;
            size_t xbase = ((size_t)(tcur * BATCH + b0g + b)) * G4 + u0 + uu;
            float gi = Cs[b * 68 + uu]      + X[xbase];
            float gf = Cs[b * 68 + 16 + uu] + X[xbase + 512];
            float gg = Cs[b * 68 + 32 + uu] + X[xbase + 1024];
            float go = Cs[b * 68 + 48 + uu] + X[xbase + 1536];
            float si = 1.f / (1.f + __expf(-gi));
            float sf = 1.f / (1.f + __expf(-gf));
            float so = 1.f / (1.f + __expf(-go));
            float c  = sf * c_s[b * 16 + uu] + si * tanhf(gg);
            float h  = so * tanhf(c);
            float m  = mask[tcur * BATCH + b0g + b];
            c *= m; h *= m;
            c_s[b * 16 + uu] = c;
            out[((size_t)(tcur * BATCH + b0g + b)) * 1024 + dir * HID + u0 + uu] = h;
            __nv_bfloat16 hbi = __float2bfloat16_rn(h);
            __nv_bfloat16 hbl = __float2bfloat16_rn(h - __bfloat162float(hbi));
            size_t hidx = ((size_t)(nxt * 2 + dir) * BATCH + b0g + b) * HID + u0 + uu;
            d_hhi[hidx] = hbi;
            d_hlo[hidx] = hbl;
        }

        // ---- grid barrier ----
        __threadfence();
        __syncthreads();
        if (tid == 0) {
            const unsigned int target = (unsigned)(step + 1);
            unsigned int arrived =
                atomicAdd((unsigned int*)&d_bar_count, 1u) + 1u;
            if (arrived == (unsigned)NBLK_REC * target) {
                __threadfence();
                atomicAdd((unsigned int*)&d_bar_gen, 1u);
            } else {
                unsigned ns = 64;
                while (d_bar_gen < target) {
                    __nanosleep(ns);
                    if (ns < 1024) ns <<= 1;
                }
            }
        }
        __syncthreads();
        __threadfence();
    }
}

// ---------------------------------------------------------------------------
// Launch
// ---------------------------------------------------------------------------
extern "C" void kernel_launch(void* const* d_in, const int* in_sizes, int n_in,
                              void* d_out, int out_size) {
    const int*   data  = (const int*)  d_in[0];
    const float* mask  = (const float*)d_in[1];
    const float* table = (const float*)d_in[2];
    const float* Wih_f = (const float*)d_in[3];
    const float* Whh_f = (const float*)d_in[4];
    const float* bih_f = (const float*)d_in[5];
    const float* bhh_f = (const float*)d_in[6];
    const float* Wih_b = (const float*)d_in[7];
    const float* Whh_b = (const float*)d_in[8];
    const float* bih_b = (const float*)d_in[9];
    const float* bhh_b = (const float*)d_in[10];
    float* out = (float*)d_out;

    (void)in_sizes; (void)n_in; (void)out_size;

    cudaFuncSetAttribute(k_recur_mma,
                         cudaFuncAttributeMaxDynamicSharedMemorySize, SMEM_RECUR);

    k_embed_cvt<<<(MROWS * (EMB / 4) + 255) / 256, 256>>>(data, table);
    k_wcvt<<<(NCOLS * (EMB / 4) + 255) / 256, 256>>>(Wih_f, Wih_b);

    dim3 ggrid(NCOLS / 128, MROWS / 128);   // 32 x 64
    k_gemm_mma<<<ggrid, 256>>>(bih_f, bhh_f, bih_b, bhh_b);

    k_init<<<512, 256>>>();

    k_recur_mma<<<NBLK_REC, 256, SMEM_RECUR>>>(Whh_f, Whh_b, mask, out);
}